// round 1
// baseline (speedup 1.0000x reference)
#include <cuda_runtime.h>
#include <math.h>

#define BB 1024
#define QQ 32
#define DD 512
#define TILE_I 128
#define TILE_K 32
#define NUM_HARD 512

// Scratch (device globals — no allocation allowed)
__device__ float g_simmax[BB * BB];   // 4 MB: sim_max[i][j] (already divided by temp)
__device__ float g_rowloss[BB];

// ---------------------------------------------------------------------------
// Kernel 1: sim_max[i][j] = max_q (fusion[i] . target[j,q]) / temp
// Block: 256 threads computes a 128(i) x 32(q, one j) tile over K=512.
// Thread t: qi = t&15 handles q columns {qi, qi+16}; ii = t>>4 handles rows
// ii*8..ii*8+7. Epilogue: max over 2 local cols + shfl over 16 lanes = max over 32 q.
// ---------------------------------------------------------------------------
__global__ __launch_bounds__(256) void sim_kernel(
    const float* __restrict__ fusion,
    const float* __restrict__ target,
    const float* __restrict__ temp_p)
{
    __shared__ float As[TILE_I][TILE_K + 1];  // +1 pad: conflict-free stores/reads
    __shared__ float Bs[QQ][TILE_K + 1];

    const int j  = blockIdx.x;
    const int i0 = blockIdx.y * TILE_I;
    const int t  = threadIdx.x;
    const int qi = t & 15;
    const int ii = t >> 4;

    float acc[8][2];
#pragma unroll
    for (int r = 0; r < 8; r++) { acc[r][0] = 0.f; acc[r][1] = 0.f; }

    const float* tgt = target + (size_t)j * QQ * DD;

    for (int k0 = 0; k0 < DD; k0 += TILE_K) {
        // Load A tile: 128 x 32 (coalesced: consecutive t -> consecutive k in a row)
#pragma unroll
        for (int p = 0; p < 16; p++) {
            int idx = p * 256 + t;
            int ai = idx >> 5;
            int ak = idx & 31;
            As[ai][ak] = fusion[(size_t)(i0 + ai) * DD + k0 + ak];
        }
        // Load B tile: 32 x 32
#pragma unroll
        for (int p = 0; p < 4; p++) {
            int idx = p * 256 + t;
            int bq = idx >> 5;
            int bk = idx & 31;
            Bs[bq][bk] = tgt[(size_t)bq * DD + k0 + bk];
        }
        __syncthreads();

#pragma unroll
        for (int kk = 0; kk < TILE_K; kk++) {
            float b0 = Bs[qi][kk];
            float b1 = Bs[qi + 16][kk];
#pragma unroll
            for (int r = 0; r < 8; r++) {
                float a = As[ii * 8 + r][kk];
                acc[r][0] = fmaf(a, b0, acc[r][0]);
                acc[r][1] = fmaf(a, b1, acc[r][1]);
            }
        }
        __syncthreads();
    }

    const float inv_temp = 1.0f / temp_p[0];
#pragma unroll
    for (int r = 0; r < 8; r++) {
        float m = fmaxf(acc[r][0], acc[r][1]);
#pragma unroll
        for (int s = 8; s >= 1; s >>= 1)
            m = fmaxf(m, __shfl_xor_sync(0xffffffffu, m, s));
        if (qi == 0)
            g_simmax[(size_t)(i0 + ii * 8 + r) * BB + j] = m * inv_temp;
    }
}

// ---------------------------------------------------------------------------
// Kernel 2: per-row loss. One block (512 threads) per row i.
//   standard: lse(full row) - pos
//   hard:     lse([pos, top-512 of off-diagonal]) - pos
// Top-512 via in-smem bitonic sort (ascending; top half = buf[512..1023]).
// ---------------------------------------------------------------------------
__global__ __launch_bounds__(512) void loss_kernel()
{
    __shared__ float row[BB];
    __shared__ float buf[BB];
    __shared__ float red[512];

    const int i = blockIdx.x;
    const int t = threadIdx.x;

    float v0 = g_simmax[(size_t)i * BB + t];
    float v1 = g_simmax[(size_t)i * BB + t + 512];
    row[t] = v0;
    row[t + 512] = v1;
    buf[t]       = (t == i)       ? -INFINITY : v0;
    buf[t + 512] = (t + 512 == i) ? -INFINITY : v1;

    // --- full-row max ---
    red[t] = fmaxf(v0, v1);
    __syncthreads();
    for (int s = 256; s > 0; s >>= 1) {
        if (t < s) red[t] = fmaxf(red[t], red[t + s]);
        __syncthreads();
    }
    float m_all = red[0];
    __syncthreads();

    // --- full-row sum of exp ---
    red[t] = expf(v0 - m_all) + expf(v1 - m_all);
    __syncthreads();
    for (int s = 256; s > 0; s >>= 1) {
        if (t < s) red[t] += red[t + s];
        __syncthreads();
    }
    float lse_all = logf(red[0]) + m_all;
    float pos = row[i];
    __syncthreads();

    // --- bitonic sort buf ascending (1024 elems, 512 threads) ---
    for (int kk = 2; kk <= BB; kk <<= 1) {
        for (int jj = kk >> 1; jj > 0; jj >>= 1) {
            __syncthreads();
#pragma unroll
            for (int u = 0; u < 2; u++) {
                int idx = t + u * 512;
                int ixj = idx ^ jj;
                if (ixj > idx) {
                    bool up = ((idx & kk) == 0);
                    float a = buf[idx], b = buf[ixj];
                    if ((a > b) == up) { buf[idx] = b; buf[ixj] = a; }
                }
            }
        }
    }
    __syncthreads();

    // --- hard-negative logsumexp over [pos, buf[512..1023]] ---
    float mh = fmaxf(pos, buf[BB - 1]);
    float part = expf(buf[512 + t] - mh);
    if (t == 0) part += expf(pos - mh);
    red[t] = part;
    __syncthreads();
    for (int s = 256; s > 0; s >>= 1) {
        if (t < s) red[t] += red[t + s];
        __syncthreads();
    }
    if (t == 0) {
        float lse_h = logf(red[0]) + mh;
        g_rowloss[i] = (lse_all - pos) + 0.5f * (lse_h - pos);
    }
}

// ---------------------------------------------------------------------------
// Kernel 3: mean over rows -> scalar output
// ---------------------------------------------------------------------------
__global__ __launch_bounds__(256) void final_kernel(float* __restrict__ out)
{
    __shared__ float red[256];
    const int t = threadIdx.x;
    float s = 0.f;
#pragma unroll
    for (int p = 0; p < 4; p++) s += g_rowloss[t + p * 256];
    red[t] = s;
    __syncthreads();
    for (int st = 128; st > 0; st >>= 1) {
        if (t < st) red[t] += red[t + st];
        __syncthreads();
    }
    if (t == 0) out[0] = red[0] / (float)BB;
}

extern "C" void kernel_launch(void* const* d_in, const int* in_sizes, int n_in,
                              void* d_out, int out_size)
{
    const float* fusion = (const float*)d_in[0];   // (1024, 512)
    const float* target = (const float*)d_in[1];   // (1024, 32, 512)
    const float* temp   = (const float*)d_in[2];   // scalar
    float* out = (float*)d_out;

    dim3 g1(BB, BB / TILE_I);   // (j, i-tile)
    sim_kernel<<<g1, 256>>>(fusion, target, temp);
    loss_kernel<<<BB, 512>>>();
    final_kernel<<<1, 256>>>(out);
}

// round 3
// speedup vs baseline: 4.3133x; 4.3133x over previous
#include <cuda_runtime.h>
#include <math.h>

#define BB 1024
#define QQ 32
#define DD 512
#define NJQ (BB * QQ)

#define CTA_M 128
#define CTA_N 256
#define CK    32
#define A_FLOATS (CTA_M * CK)
#define B_FLOATS (CTA_N * CK)
#define STAGE_FLOATS (A_FLOATS + B_FLOATS)
#define SMEM_BYTES (2 * STAGE_FLOATS * 4)

__device__ float g_simmax[BB * BB];
__device__ float g_rowloss[BB];
__device__ float g_fusion_t[BB * DD];
__device__ float g_target_t[NJQ * DD];

// ---------------------------------------------------------------------------
// tf32 RNA conversion into device-global staging (dst selected by flag to
// avoid needing cudaGetSymbolAddress on the host side).
// ---------------------------------------------------------------------------
__global__ __launch_bounds__(256) void cvt_tf32_kernel(
    const float4* __restrict__ in, int n4, int which)
{
    float4* out = which ? (float4*)g_target_t : (float4*)g_fusion_t;
    for (int i = blockIdx.x * blockDim.x + threadIdx.x; i < n4;
         i += gridDim.x * blockDim.x) {
        float4 v = in[i];
        unsigned o0, o1, o2, o3;
        asm("cvt.rna.tf32.f32 %0, %1;" : "=r"(o0) : "f"(v.x));
        asm("cvt.rna.tf32.f32 %0, %1;" : "=r"(o1) : "f"(v.y));
        asm("cvt.rna.tf32.f32 %0, %1;" : "=r"(o2) : "f"(v.z));
        asm("cvt.rna.tf32.f32 %0, %1;" : "=r"(o3) : "f"(v.w));
        float4 w;
        w.x = __uint_as_float(o0); w.y = __uint_as_float(o1);
        w.z = __uint_as_float(o2); w.w = __uint_as_float(o3);
        out[i] = w;
    }
}

// ---------------------------------------------------------------------------
// Tensor-core GEMM + max-over-q epilogue (tf32 mma.m16n8k8).
// CTA 128x256, K-chunk 32, 8 warps (2x4) of 64x64 each.
// Smem swizzle: phys col = k ^ (4*(row&7)): conflict-free cp.async stores
// and conflict-free fragment LDS.32 loads.
// ---------------------------------------------------------------------------
__device__ __forceinline__ void mma_tf32(float c[4], unsigned a0, unsigned a1,
                                         unsigned a2, unsigned a3,
                                         unsigned b0, unsigned b1)
{
    asm volatile(
        "mma.sync.aligned.m16n8k8.row.col.f32.tf32.tf32.f32 "
        "{%0,%1,%2,%3},{%4,%5,%6,%7},{%8,%9},{%0,%1,%2,%3};"
        : "+f"(c[0]), "+f"(c[1]), "+f"(c[2]), "+f"(c[3])
        : "r"(a0), "r"(a1), "r"(a2), "r"(a3), "r"(b0), "r"(b1));
}

__device__ __forceinline__ void cp16(unsigned saddr, const void* gaddr)
{
    asm volatile("cp.async.cg.shared.global [%0], [%1], 16;"
                 :: "r"(saddr), "l"(gaddr));
}

__global__ __launch_bounds__(256, 1) void sim_tc(const float* __restrict__ temp_p)
{
    extern __shared__ float sm[];
    const int t    = threadIdx.x;
    const int wid  = t >> 5;
    const int lane = t & 31;
    const int g    = lane >> 2;
    const int tg   = lane & 3;
    const int g4   = g << 2;
    const int wm   = (wid >> 2) * 64;
    const int wn   = (wid & 3) * 64;
    const int i0   = blockIdx.x * CTA_M;
    const int jq0  = blockIdx.y * CTA_N;

    float c[4][8][4];
#pragma unroll
    for (int mf = 0; mf < 4; mf++)
#pragma unroll
        for (int nf = 0; nf < 8; nf++)
#pragma unroll
            for (int r = 0; r < 4; r++) c[mf][nf][r] = 0.f;

    const unsigned sbase = (unsigned)__cvta_generic_to_shared(sm);

    const float* agp[4]; unsigned aso[4];
#pragma unroll
    for (int p = 0; p < 4; p++) {
        int idx4 = t + p * 256;
        int mloc = idx4 >> 3, kb = idx4 & 7;
        agp[p] = g_fusion_t + (size_t)(i0 + mloc) * DD + kb * 4;
        aso[p] = (unsigned)((mloc * CK + ((kb ^ (mloc & 7)) << 2)) << 2);
    }
    const float* bgp[8]; unsigned bso[8];
#pragma unroll
    for (int p = 0; p < 8; p++) {
        int idx4 = t + p * 256;
        int nloc = idx4 >> 3, kb = idx4 & 7;
        bgp[p] = g_target_t + (size_t)(jq0 + nloc) * DD + kb * 4;
        bso[p] = (unsigned)((nloc * CK + ((kb ^ (nloc & 7)) << 2)) << 2);
    }

    {
        unsigned sb  = sbase;
        unsigned sbB = sb + A_FLOATS * 4;
#pragma unroll
        for (int p = 0; p < 4; p++) cp16(sb + aso[p], agp[p]);
#pragma unroll
        for (int p = 0; p < 8; p++) cp16(sbB + bso[p], bgp[p]);
        asm volatile("cp.async.commit_group;" ::: "memory");
    }

    for (int ch = 0; ch < DD / CK; ch++) {
        const int st = ch & 1;
        asm volatile("cp.async.wait_group 0;" ::: "memory");
        __syncthreads();

        if (ch < DD / CK - 1) {
            const int k0 = (ch + 1) * CK;
            unsigned sb  = sbase + (unsigned)((st ^ 1) * STAGE_FLOATS * 4);
            unsigned sbB = sb + A_FLOATS * 4;
#pragma unroll
            for (int p = 0; p < 4; p++) cp16(sb + aso[p], agp[p] + k0);
#pragma unroll
            for (int p = 0; p < 8; p++) cp16(sbB + bso[p], bgp[p] + k0);
            asm volatile("cp.async.commit_group;" ::: "memory");
        }

        const unsigned* sA = reinterpret_cast<const unsigned*>(sm + st * STAGE_FLOATS);
        const unsigned* sB = sA + A_FLOATS;

#pragma unroll
        for (int s = 0; s < 4; s++) {
            const int kx0 = ((s << 3) + tg) ^ g4;
            const int kx1 = ((s << 3) + tg + 4) ^ g4;
            unsigned a[4][4];
#pragma unroll
            for (int mf = 0; mf < 4; mf++) {
                const int r0 = (wm + (mf << 4) + g) * CK;
                a[mf][0] = sA[r0 + kx0];
                a[mf][1] = sA[r0 + 8 * CK + kx0];
                a[mf][2] = sA[r0 + kx1];
                a[mf][3] = sA[r0 + 8 * CK + kx1];
            }
#pragma unroll
            for (int nf = 0; nf < 8; nf++) {
                const int n0 = (wn + (nf << 3) + g) * CK;
                unsigned b0 = sB[n0 + kx0];
                unsigned b1 = sB[n0 + kx1];
#pragma unroll
                for (int mf = 0; mf < 4; mf++)
                    mma_tf32(c[mf][nf], a[mf][0], a[mf][1], a[mf][2], a[mf][3], b0, b1);
            }
        }
    }

    const float invt = 1.0f / temp_p[0];
#pragma unroll
    for (int mf = 0; mf < 4; mf++) {
#pragma unroll
        for (int h = 0; h < 2; h++) {
#pragma unroll
            for (int jh = 0; jh < 2; jh++) {
                float v = -INFINITY;
#pragma unroll
                for (int nf = 4 * jh; nf < 4 * jh + 4; nf++)
                    v = fmaxf(v, fmaxf(c[mf][nf][2 * h], c[mf][nf][2 * h + 1]));
                v = fmaxf(v, __shfl_xor_sync(0xffffffffu, v, 1));
                v = fmaxf(v, __shfl_xor_sync(0xffffffffu, v, 2));
                if (tg == 0) {
                    int row = i0 + wm + (mf << 4) + (h << 3) + g;
                    int j   = ((jq0 + wn) >> 5) + jh;
                    g_simmax[(size_t)row * BB + j] = v * invt;
                }
            }
        }
    }
}

// ---------------------------------------------------------------------------
// Per-row loss (unchanged)
// ---------------------------------------------------------------------------
__global__ __launch_bounds__(512) void loss_kernel()
{
    __shared__ float row[BB];
    __shared__ float buf[BB];
    __shared__ float red[512];

    const int i = blockIdx.x;
    const int t = threadIdx.x;

    float v0 = g_simmax[(size_t)i * BB + t];
    float v1 = g_simmax[(size_t)i * BB + t + 512];
    row[t] = v0;
    row[t + 512] = v1;
    buf[t]       = (t == i)       ? -INFINITY : v0;
    buf[t + 512] = (t + 512 == i) ? -INFINITY : v1;

    red[t] = fmaxf(v0, v1);
    __syncthreads();
    for (int s = 256; s > 0; s >>= 1) {
        if (t < s) red[t] = fmaxf(red[t], red[t + s]);
        __syncthreads();
    }
    float m_all = red[0];
    __syncthreads();

    red[t] = expf(v0 - m_all) + expf(v1 - m_all);
    __syncthreads();
    for (int s = 256; s > 0; s >>= 1) {
        if (t < s) red[t] += red[t + s];
        __syncthreads();
    }
    float lse_all = logf(red[0]) + m_all;
    float pos = row[i];
    __syncthreads();

    for (int kk = 2; kk <= BB; kk <<= 1) {
        for (int jj = kk >> 1; jj > 0; jj >>= 1) {
            __syncthreads();
#pragma unroll
            for (int u = 0; u < 2; u++) {
                int idx = t + u * 512;
                int ixj = idx ^ jj;
                if (ixj > idx) {
                    bool up = ((idx & kk) == 0);
                    float a = buf[idx], b = buf[ixj];
                    if ((a > b) == up) { buf[idx] = b; buf[ixj] = a; }
                }
            }
        }
    }
    __syncthreads();

    float mh = fmaxf(pos, buf[BB - 1]);
    float part = expf(buf[512 + t] - mh);
    if (t == 0) part += expf(pos - mh);
    red[t] = part;
    __syncthreads();
    for (int s = 256; s > 0; s >>= 1) {
        if (t < s) red[t] += red[t + s];
        __syncthreads();
    }
    if (t == 0) {
        float lse_h = logf(red[0]) + mh;
        g_rowloss[i] = (lse_all - pos) + 0.5f * (lse_h - pos);
    }
}

__global__ __launch_bounds__(256) void final_kernel(float* __restrict__ out)
{
    __shared__ float red[256];
    const int t = threadIdx.x;
    float s = 0.f;
#pragma unroll
    for (int p = 0; p < 4; p++) s += g_rowloss[t + p * 256];
    red[t] = s;
    __syncthreads();
    for (int st = 128; st > 0; st >>= 1) {
        if (t < st) red[t] += red[t + st];
        __syncthreads();
    }
    if (t == 0) out[0] = red[0] / (float)BB;
}

extern "C" void kernel_launch(void* const* d_in, const int* in_sizes, int n_in,
                              void* d_out, int out_size)
{
    const float* fusion = (const float*)d_in[0];
    const float* target = (const float*)d_in[1];
    const float* temp   = (const float*)d_in[2];
    float* out = (float*)d_out;

    cudaFuncSetAttribute(sim_tc, cudaFuncAttributeMaxDynamicSharedMemorySize,
                         SMEM_BYTES);

    cvt_tf32_kernel<<<256, 256>>>((const float4*)fusion, BB * DD / 4, 0);
    cvt_tf32_kernel<<<2048, 256>>>((const float4*)target, NJQ * DD / 4, 1);

    dim3 grid(BB / CTA_M, NJQ / CTA_N);   // (8, 128)
    sim_tc<<<grid, 256, SMEM_BYTES>>>(temp);

    loss_kernel<<<BB, 512>>>();
    final_kernel<<<1, 256>>>(out);
}

// round 7
// speedup vs baseline: 4.8805x; 1.1315x over previous
#include <cuda_runtime.h>
#include <math.h>
#include <stdint.h>

#define BB 1024
#define QQ 32
#define DD 512
#define NJQ (BB * QQ)

#define CTA_M 128
#define CTA_N 256
#define CK    32
#define A_FLOATS (CTA_M * CK)
#define B_FLOATS (CTA_N * CK)
#define STAGE_FLOATS (A_FLOATS + B_FLOATS)
#define SMEM_BYTES (2 * STAGE_FLOATS * 4)
#define NUM_HARD 512

__device__ float g_simmax[BB * BB];
__device__ float g_rowloss[BB];

// ---------------------------------------------------------------------------
// Tensor-core GEMM + max-over-q epilogue (tf32 mma.m16n8k8, raw fp32 inputs —
// HW truncates to tf32; error is a near-uniform logit scale, cancels in softmax).
// CTA 128x256, K-chunk 32, 8 warps (2x4) of 64x64 each.
// Smem swizzle: 16B-unit col = kb ^ (row&7): conflict-free cp.async stores and
// conflict-free fragment LDS.32 loads.
// ---------------------------------------------------------------------------
__device__ __forceinline__ void mma_tf32(float c[4], unsigned a0, unsigned a1,
                                         unsigned a2, unsigned a3,
                                         unsigned b0, unsigned b1)
{
    asm volatile(
        "mma.sync.aligned.m16n8k8.row.col.f32.tf32.tf32.f32 "
        "{%0,%1,%2,%3},{%4,%5,%6,%7},{%8,%9},{%0,%1,%2,%3};"
        : "+f"(c[0]), "+f"(c[1]), "+f"(c[2]), "+f"(c[3])
        : "r"(a0), "r"(a1), "r"(a2), "r"(a3), "r"(b0), "r"(b1));
}

__device__ __forceinline__ void cp16(unsigned saddr, const void* gaddr)
{
    asm volatile("cp.async.cg.shared.global [%0], [%1], 16;"
                 :: "r"(saddr), "l"(gaddr));
}

__global__ __launch_bounds__(256, 1) void sim_tc(
    const float* __restrict__ fusion,
    const float* __restrict__ target,
    const float* __restrict__ temp_p)
{
    extern __shared__ float sm[];
    const int t    = threadIdx.x;
    const int wid  = t >> 5;
    const int lane = t & 31;
    const int g    = lane >> 2;
    const int tg   = lane & 3;
    const int g4   = g << 2;
    const int wm   = (wid >> 2) * 64;
    const int wn   = (wid & 3) * 64;
    const int i0   = blockIdx.x * CTA_M;
    const int jq0  = blockIdx.y * CTA_N;

    float c[4][8][4];
#pragma unroll
    for (int mf = 0; mf < 4; mf++)
#pragma unroll
        for (int nf = 0; nf < 8; nf++)
#pragma unroll
            for (int r = 0; r < 4; r++) c[mf][nf][r] = 0.f;

    const unsigned sbase = (unsigned)__cvta_generic_to_shared(sm);

    const float* agp[4]; unsigned aso[4];
#pragma unroll
    for (int p = 0; p < 4; p++) {
        int idx4 = t + p * 256;
        int mloc = idx4 >> 3, kb = idx4 & 7;
        agp[p] = fusion + (size_t)(i0 + mloc) * DD + kb * 4;
        aso[p] = (unsigned)((mloc * CK + ((kb ^ (mloc & 7)) << 2)) << 2);
    }
    const float* bgp[8]; unsigned bso[8];
#pragma unroll
    for (int p = 0; p < 8; p++) {
        int idx4 = t + p * 256;
        int nloc = idx4 >> 3, kb = idx4 & 7;
        bgp[p] = target + (size_t)(jq0 + nloc) * DD + kb * 4;
        bso[p] = (unsigned)((nloc * CK + ((kb ^ (nloc & 7)) << 2)) << 2);
    }

    {
        unsigned sb  = sbase;
        unsigned sbB = sb + A_FLOATS * 4;
#pragma unroll
        for (int p = 0; p < 4; p++) cp16(sb + aso[p], agp[p]);
#pragma unroll
        for (int p = 0; p < 8; p++) cp16(sbB + bso[p], bgp[p]);
        asm volatile("cp.async.commit_group;" ::: "memory");
    }

    for (int ch = 0; ch < DD / CK; ch++) {
        const int st = ch & 1;
        asm volatile("cp.async.wait_group 0;" ::: "memory");
        __syncthreads();

        if (ch < DD / CK - 1) {
            const int k0 = (ch + 1) * CK;
            unsigned sb  = sbase + (unsigned)((st ^ 1) * STAGE_FLOATS * 4);
            unsigned sbB = sb + A_FLOATS * 4;
#pragma unroll
            for (int p = 0; p < 4; p++) cp16(sb + aso[p], agp[p] + k0);
#pragma unroll
            for (int p = 0; p < 8; p++) cp16(sbB + bso[p], bgp[p] + k0);
            asm volatile("cp.async.commit_group;" ::: "memory");
        }

        const unsigned* sA = reinterpret_cast<const unsigned*>(sm + st * STAGE_FLOATS);
        const unsigned* sB = sA + A_FLOATS;

#pragma unroll
        for (int s = 0; s < 4; s++) {
            const int kx0 = ((s << 3) + tg) ^ g4;
            const int kx1 = ((s << 3) + tg + 4) ^ g4;
            unsigned a[4][4];
#pragma unroll
            for (int mf = 0; mf < 4; mf++) {
                const int r0 = (wm + (mf << 4) + g) * CK;
                a[mf][0] = sA[r0 + kx0];
                a[mf][1] = sA[r0 + 8 * CK + kx0];
                a[mf][2] = sA[r0 + kx1];
                a[mf][3] = sA[r0 + 8 * CK + kx1];
            }
#pragma unroll
            for (int nf = 0; nf < 8; nf++) {
                const int n0 = (wn + (nf << 3) + g) * CK;
                unsigned b0 = sB[n0 + kx0];
                unsigned b1 = sB[n0 + kx1];
#pragma unroll
                for (int mf = 0; mf < 4; mf++)
                    mma_tf32(c[mf][nf], a[mf][0], a[mf][1], a[mf][2], a[mf][3], b0, b1);
            }
        }
    }

    const float invt = 1.0f / temp_p[0];
#pragma unroll
    for (int mf = 0; mf < 4; mf++) {
#pragma unroll
        for (int h = 0; h < 2; h++) {
#pragma unroll
            for (int jh = 0; jh < 2; jh++) {
                float v = -INFINITY;
#pragma unroll
                for (int nf = 4 * jh; nf < 4 * jh + 4; nf++)
                    v = fmaxf(v, fmaxf(c[mf][nf][2 * h], c[mf][nf][2 * h + 1]));
                v = fmaxf(v, __shfl_xor_sync(0xffffffffu, v, 1));
                v = fmaxf(v, __shfl_xor_sync(0xffffffffu, v, 2));
                if (tg == 0) {
                    int row = i0 + wm + (mf << 4) + (h << 3) + g;
                    int j   = ((jq0 + wn) >> 5) + jh;
                    g_simmax[(size_t)row * BB + j] = v * invt;
                }
            }
        }
    }
}

// ---------------------------------------------------------------------------
// Per-row loss. One 1024-thread block per row.
// Top-512 via exact 32-step binary search on monotonic uint keys using
// __syncthreads_count — replaces the bitonic sort.
// ---------------------------------------------------------------------------
__device__ __forceinline__ unsigned f2key(float f)
{
    unsigned b = __float_as_uint(f);
    return (b & 0x80000000u) ? ~b : (b | 0x80000000u);
}
__device__ __forceinline__ float key2f(unsigned k)
{
    return __uint_as_float((k & 0x80000000u) ? (k ^ 0x80000000u) : ~k);
}

__global__ __launch_bounds__(1024) void loss_kernel()
{
    __shared__ float red[1024];
    __shared__ float s_pos;

    const int i = blockIdx.x;
    const int t = threadIdx.x;

    const float v = g_simmax[(size_t)i * BB + t];
    const bool diag = (t == i);
    const float w = diag ? -INFINITY : v;
    if (diag) s_pos = v;

    // --- full-row max ---
    red[t] = v;
    __syncthreads();
#pragma unroll
    for (int s = 512; s > 0; s >>= 1) {
        if (t < s) red[t] = fmaxf(red[t], red[t + s]);
        __syncthreads();
    }
    const float m_all = red[0];
    const float pos = s_pos;
    __syncthreads();

    // --- full-row sum of exp ---
    const float ev = expf(v - m_all);
    red[t] = ev;
    __syncthreads();
#pragma unroll
    for (int s = 512; s > 0; s >>= 1) {
        if (t < s) red[t] += red[t + s];
        __syncthreads();
    }
    const float lse_all = logf(red[0]) + m_all;
    __syncthreads();

    // --- exact 512th-largest off-diagonal via bit binary search ---
    const unsigned key = f2key(w);
    unsigned lo = 0u, hi = 0xFFFFFFFFu;
    for (int it = 0; it < 32; it++) {
        unsigned mid = lo + ((hi - lo) >> 1);
        int cnt = __syncthreads_count(key > mid);
        if (cnt >= NUM_HARD) lo = mid; else hi = mid;
    }
    // hi == 512th-largest key exactly
    const float kthf = key2f(hi);
    const int cnt_gt = __syncthreads_count(key > hi);

    // --- hard logsumexp over [pos, top-512] (stable with m_all >= all) ---
    float e = (key > hi) ? expf(w - m_all) : 0.f;
    if (t == 0)
        e += (float)(NUM_HARD - cnt_gt) * expf(kthf - m_all) + expf(pos - m_all);
    red[t] = e;
    __syncthreads();
#pragma unroll
    for (int s = 512; s > 0; s >>= 1) {
        if (t < s) red[t] += red[t + s];
        __syncthreads();
    }
    if (t == 0) {
        const float lse_h = logf(red[0]) + m_all;
        g_rowloss[i] = (lse_all - pos) + 0.5f * (lse_h - pos);
    }
}

__global__ __launch_bounds__(256) void final_kernel(float* __restrict__ out)
{
    __shared__ float red[256];
    const int t = threadIdx.x;
    float s = 0.f;
#pragma unroll
    for (int p = 0; p < 4; p++) s += g_rowloss[t + p * 256];
    red[t] = s;
    __syncthreads();
    for (int st = 128; st > 0; st >>= 1) {
        if (t < st) red[t] += red[t + st];
        __syncthreads();
    }
    if (t == 0) out[0] = red[0] / (float)BB;
}

extern "C" void kernel_launch(void* const* d_in, const int* in_sizes, int n_in,
                              void* d_out, int out_size)
{
    const float* fusion = (const float*)d_in[0];
    const float* target = (const float*)d_in[1];
    const float* temp   = (const float*)d_in[2];
    float* out = (float*)d_out;

    cudaFuncSetAttribute(sim_tc, cudaFuncAttributeMaxDynamicSharedMemorySize,
                         SMEM_BYTES);

    dim3 grid(BB / CTA_M, NJQ / CTA_N);   // (8, 128)
    sim_tc<<<grid, 256, SMEM_BYTES>>>(fusion, target, temp);

    loss_kernel<<<BB, 1024>>>();
    final_kernel<<<1, 256>>>(out);
}

// round 8
// speedup vs baseline: 7.7522x; 1.5884x over previous
#include <cuda_runtime.h>
#include <cuda_bf16.h>
#include <math.h>
#include <stdint.h>

#define BB 1024
#define QQ 32
#define DD 512
#define NJQ (BB * QQ)
#define NUM_HARD 512

#define CTA_M 128
#define CTA_N 256
#define CKH   64                       // K halves per chunk (128 bytes/row)
#define NCHUNK (DD / CKH)              // 8
#define A_BYTES (CTA_M * CKH * 2)      // 16384
#define B_BYTES (CTA_N * CKH * 2)      // 32768
#define STAGE_BYTES (A_BYTES + B_BYTES)  // 49152
#define NSTAGE 3
#define SMEM_BYTES (NSTAGE * STAGE_BYTES) // 147456

__device__ float g_simmax[BB * BB];
__device__ float g_rowloss[BB];
__device__ uint4 g_fusion_h[BB * DD / 8];      // bf16 staging (16B-aligned)
__device__ uint4 g_target_h[NJQ * DD / 8];

// ---------------------------------------------------------------------------
// fp32 -> bf16 (RNE) conversion pre-pass
// ---------------------------------------------------------------------------
__global__ __launch_bounds__(256) void cvt_bf16_kernel(
    const float4* __restrict__ in, int n4, int which)
{
    uint2* out = which ? (uint2*)g_target_h : (uint2*)g_fusion_h;
    for (int i = blockIdx.x * blockDim.x + threadIdx.x; i < n4;
         i += gridDim.x * blockDim.x) {
        float4 v = in[i];
        __nv_bfloat162 h0 = __float22bfloat162_rn(make_float2(v.x, v.y));
        __nv_bfloat162 h1 = __float22bfloat162_rn(make_float2(v.z, v.w));
        uint2 o;
        o.x = *(unsigned*)&h0;
        o.y = *(unsigned*)&h1;
        out[i] = o;
    }
}

// ---------------------------------------------------------------------------
// bf16 tensor-core GEMM + max-over-q epilogue (mma.m16n8k16, fp32 accum).
// CTA 128x256, K-chunk 64 halves, 8 warps (2x4) of 64x64; 3-stage cp.async.
// Swizzle identical to tf32 version (rows are 32 x 32-bit words either way).
// ---------------------------------------------------------------------------
__device__ __forceinline__ void mma_bf16(float c[4], unsigned a0, unsigned a1,
                                         unsigned a2, unsigned a3,
                                         unsigned b0, unsigned b1)
{
    asm volatile(
        "mma.sync.aligned.m16n8k16.row.col.f32.bf16.bf16.f32 "
        "{%0,%1,%2,%3},{%4,%5,%6,%7},{%8,%9},{%0,%1,%2,%3};"
        : "+f"(c[0]), "+f"(c[1]), "+f"(c[2]), "+f"(c[3])
        : "r"(a0), "r"(a1), "r"(a2), "r"(a3), "r"(b0), "r"(b1));
}

__device__ __forceinline__ void cp16(unsigned saddr, const void* gaddr)
{
    asm volatile("cp.async.cg.shared.global [%0], [%1], 16;"
                 :: "r"(saddr), "l"(gaddr));
}

__global__ __launch_bounds__(256, 1) void sim_tc(const float* __restrict__ temp_p)
{
    extern __shared__ float sm[];
    const int t    = threadIdx.x;
    const int wid  = t >> 5;
    const int lane = t & 31;
    const int g    = lane >> 2;
    const int tg   = lane & 3;
    const int g4   = g << 2;
    const int wm   = (wid >> 2) * 64;
    const int wn   = (wid & 3) * 64;
    const int i0   = blockIdx.x * CTA_M;
    const int jq0  = blockIdx.y * CTA_N;

    float c[4][8][4];
#pragma unroll
    for (int mf = 0; mf < 4; mf++)
#pragma unroll
        for (int nf = 0; nf < 8; nf++)
#pragma unroll
            for (int r = 0; r < 4; r++) c[mf][nf][r] = 0.f;

    const unsigned sbase = (unsigned)__cvta_generic_to_shared(sm);
    const __nv_bfloat16* fus = (const __nv_bfloat16*)g_fusion_h;
    const __nv_bfloat16* tgt = (const __nv_bfloat16*)g_target_h;

    // A: 16KB/stage = 1024 x 16B -> 4 per thread; B: 32KB -> 8 per thread.
    const __nv_bfloat16* agp[4]; unsigned aso[4];
#pragma unroll
    for (int p = 0; p < 4; p++) {
        int idx4 = t + p * 256;
        int row = idx4 >> 3, kb = idx4 & 7;     // 8 x 16B chunks per 128B row
        agp[p] = fus + (size_t)(i0 + row) * DD + kb * 8;
        aso[p] = (unsigned)(row * 128 + ((kb ^ (row & 7)) << 4));
    }
    const __nv_bfloat16* bgp[8]; unsigned bso[8];
#pragma unroll
    for (int p = 0; p < 8; p++) {
        int idx4 = t + p * 256;
        int row = idx4 >> 3, kb = idx4 & 7;
        bgp[p] = tgt + (size_t)(jq0 + row) * DD + kb * 8;
        bso[p] = (unsigned)(A_BYTES + row * 128 + ((kb ^ (row & 7)) << 4));
    }

    // prologue: stage chunks 0 and 1
#pragma unroll
    for (int pc = 0; pc < 2; pc++) {
        unsigned sb = sbase + pc * STAGE_BYTES;
#pragma unroll
        for (int p = 0; p < 4; p++) cp16(sb + aso[p], agp[p] + pc * CKH);
#pragma unroll
        for (int p = 0; p < 8; p++) cp16(sb + bso[p], bgp[p] + pc * CKH);
        asm volatile("cp.async.commit_group;" ::: "memory");
    }

    for (int ch = 0; ch < NCHUNK; ch++) {
        if (ch == NCHUNK - 1)
            asm volatile("cp.async.wait_group 0;" ::: "memory");
        else
            asm volatile("cp.async.wait_group 1;" ::: "memory");
        __syncthreads();

        if (ch + 2 < NCHUNK) {
            const int k0 = (ch + 2) * CKH;
            unsigned sb = sbase + (unsigned)(((ch + 2) % NSTAGE) * STAGE_BYTES);
#pragma unroll
            for (int p = 0; p < 4; p++) cp16(sb + aso[p], agp[p] + k0);
#pragma unroll
            for (int p = 0; p < 8; p++) cp16(sb + bso[p], bgp[p] + k0);
            asm volatile("cp.async.commit_group;" ::: "memory");
        }

        const unsigned* sA = reinterpret_cast<const unsigned*>(sm)
                           + (size_t)(ch % NSTAGE) * (STAGE_BYTES / 4);
        const unsigned* sB = sA + A_BYTES / 4;

#pragma unroll
        for (int s = 0; s < 4; s++) {             // 4 k-steps of 16
            const int kx0 = ((s << 3) + tg) ^ g4;
            const int kx1 = ((s << 3) + tg + 4) ^ g4;
            unsigned a[4][4];
#pragma unroll
            for (int mf = 0; mf < 4; mf++) {
                const int r0 = (wm + (mf << 4) + g) * 32;   // 32 words/row
                a[mf][0] = sA[r0 + kx0];
                a[mf][1] = sA[r0 + 256 + kx0];              // +8 rows
                a[mf][2] = sA[r0 + kx1];
                a[mf][3] = sA[r0 + 256 + kx1];
            }
#pragma unroll
            for (int nf = 0; nf < 8; nf++) {
                const int n0 = (wn + (nf << 3) + g) * 32;
                unsigned b0 = sB[n0 + kx0];
                unsigned b1 = sB[n0 + kx1];
#pragma unroll
                for (int mf = 0; mf < 4; mf++)
                    mma_bf16(c[mf][nf], a[mf][0], a[mf][1], a[mf][2], a[mf][3], b0, b1);
            }
        }
    }

    const float invt = 1.0f / temp_p[0];
#pragma unroll
    for (int mf = 0; mf < 4; mf++) {
#pragma unroll
        for (int h = 0; h < 2; h++) {
#pragma unroll
            for (int jh = 0; jh < 2; jh++) {
                float v = -INFINITY;
#pragma unroll
                for (int nf = 4 * jh; nf < 4 * jh + 4; nf++)
                    v = fmaxf(v, fmaxf(c[mf][nf][2 * h], c[mf][nf][2 * h + 1]));
                v = fmaxf(v, __shfl_xor_sync(0xffffffffu, v, 1));
                v = fmaxf(v, __shfl_xor_sync(0xffffffffu, v, 2));
                if (tg == 0) {
                    int row = i0 + wm + (mf << 4) + (h << 3) + g;
                    int j   = ((jq0 + wn) >> 5) + jh;
                    g_simmax[(size_t)row * BB + j] = v * invt;
                }
            }
        }
    }
}

// ---------------------------------------------------------------------------
// Per-row loss: ONE WARP per row, all 1024 values in registers (32/lane).
// Exact top-512 threshold via 32-step binary search with __reduce_add_sync.
// No block barriers, no shared memory.
// ---------------------------------------------------------------------------
__device__ __forceinline__ unsigned f2key(float f)
{
    unsigned b = __float_as_uint(f);
    return (b & 0x80000000u) ? ~b : (b | 0x80000000u);
}
__device__ __forceinline__ float key2f(unsigned k)
{
    return __uint_as_float((k & 0x80000000u) ? (k ^ 0x80000000u) : ~k);
}

__global__ __launch_bounds__(256) void loss_warp()
{
    const int lane = threadIdx.x & 31;
    const int i = (blockIdx.x << 3) + (threadIdx.x >> 5);
    const float* rowp = g_simmax + (size_t)i * BB;

    float v[32];
    float m = -INFINITY, posl = 0.f;
#pragma unroll
    for (int r = 0; r < 32; r++) {
        v[r] = rowp[(r << 5) + lane];
        m = fmaxf(m, v[r]);
        if ((r << 5) + lane == i) posl = v[r];
    }
#pragma unroll
    for (int s = 16; s >= 1; s >>= 1)
        m = fmaxf(m, __shfl_xor_sync(0xffffffffu, m, s));
    float pos = posl;
#pragma unroll
    for (int s = 16; s >= 1; s >>= 1)
        pos += __shfl_xor_sync(0xffffffffu, pos, s);

    float ev[32]; unsigned key[32];
    float sum = 0.f;
#pragma unroll
    for (int r = 0; r < 32; r++) {
        ev[r] = expf(v[r] - m);
        sum += ev[r];
        key[r] = ((r << 5) + lane == i) ? 0u : f2key(v[r]);
    }
#pragma unroll
    for (int s = 16; s >= 1; s >>= 1)
        sum += __shfl_xor_sync(0xffffffffu, sum, s);
    const float lse_all = logf(sum) + m;

    // exact 512th-largest off-diagonal key
    unsigned lo = 0u, hi = 0xFFFFFFFFu;
    for (int it = 0; it < 32; it++) {
        unsigned mid = lo + ((hi - lo) >> 1);
        unsigned cl = 0;
#pragma unroll
        for (int r = 0; r < 32; r++) cl += (key[r] > mid);
        unsigned cnt = __reduce_add_sync(0xffffffffu, cl);
        if (cnt >= NUM_HARD) lo = mid; else hi = mid;
    }

    unsigned cgl = 0; float hsum = 0.f;
#pragma unroll
    for (int r = 0; r < 32; r++) {
        if (key[r] > hi) { cgl++; hsum += ev[r]; }
    }
    unsigned cgt = __reduce_add_sync(0xffffffffu, cgl);
#pragma unroll
    for (int s = 16; s >= 1; s >>= 1)
        hsum += __shfl_xor_sync(0xffffffffu, hsum, s);
    hsum += (float)(NUM_HARD - cgt) * expf(key2f(hi) - m) + expf(pos - m);

    if (lane == 0) {
        const float lse_h = logf(hsum) + m;
        g_rowloss[i] = (lse_all - pos) + 0.5f * (lse_h - pos);
    }
}

__global__ __launch_bounds__(256) void final_kernel(float* __restrict__ out)
{
    __shared__ float red[256];
    const int t = threadIdx.x;
    float s = 0.f;
#pragma unroll
    for (int p = 0; p < 4; p++) s += g_rowloss[t + p * 256];
    red[t] = s;
    __syncthreads();
    for (int st = 128; st > 0; st >>= 1) {
        if (t < st) red[t] += red[t + st];
        __syncthreads();
    }
    if (t == 0) out[0] = red[0] / (float)BB;
}

extern "C" void kernel_launch(void* const* d_in, const int* in_sizes, int n_in,
                              void* d_out, int out_size)
{
    const float* fusion = (const float*)d_in[0];
    const float* target = (const float*)d_in[1];
    const float* temp   = (const float*)d_in[2];
    float* out = (float*)d_out;

    cudaFuncSetAttribute(sim_tc, cudaFuncAttributeMaxDynamicSharedMemorySize,
                         SMEM_BYTES);

    cvt_bf16_kernel<<<128, 256>>>((const float4*)fusion, BB * DD / 4, 0);
    cvt_bf16_kernel<<<2048, 256>>>((const float4*)target, NJQ * DD / 4, 1);

    dim3 grid(BB / CTA_M, NJQ / CTA_N);   // (8, 128)
    sim_tc<<<grid, 256, SMEM_BYTES>>>(temp);

    loss_warp<<<BB / 8, 256>>>();
    final_kernel<<<1, 256>>>(out);
}

// round 9
// speedup vs baseline: 8.1522x; 1.0516x over previous
#include <cuda_runtime.h>
#include <cuda_bf16.h>
#include <math.h>
#include <stdint.h>

#define BB 1024
#define QQ 32
#define DD 512
#define NJQ (BB * QQ)
#define NUM_HARD 512

#define CTA_M 128
#define CTA_N 256
#define CKH   64                         // K halves per chunk (128 B/row)
#define NCHUNK (DD / CKH)                // 8
#define A_BYTES (CTA_M * CKH * 2)        // 16384
#define B_BYTES (CTA_N * CKH * 2)        // 32768
#define STAGE_BYTES (A_BYTES + B_BYTES)  // 49152
#define NSTAGE 3
#define SMEM_BYTES (NSTAGE * STAGE_BYTES)

#define FN4 (BB * DD / 4)                // fusion float4 count

__device__ float g_simmax[BB * BB];
__device__ float g_rowloss[BB];
__device__ uint4 g_fusion_h[BB * DD / 8];
__device__ uint4 g_target_h[NJQ * DD / 8];

// ---------------------------------------------------------------------------
// fp32 -> bf16 (RNE) conversion, both tensors in one launch
// ---------------------------------------------------------------------------
__global__ __launch_bounds__(256) void cvt_bf16_kernel(
    const float4* __restrict__ fus, const float4* __restrict__ tgt)
{
    const int n4 = FN4 + NJQ * DD / 4;
    for (int i = blockIdx.x * blockDim.x + threadIdx.x; i < n4;
         i += gridDim.x * blockDim.x) {
        const bool isf = (i < FN4);
        float4 v = isf ? fus[i] : tgt[i - FN4];
        __nv_bfloat162 h0 = __float22bfloat162_rn(make_float2(v.x, v.y));
        __nv_bfloat162 h1 = __float22bfloat162_rn(make_float2(v.z, v.w));
        uint2 o;
        o.x = *(unsigned*)&h0;
        o.y = *(unsigned*)&h1;
        if (isf) ((uint2*)g_fusion_h)[i] = o;
        else     ((uint2*)g_target_h)[i - FN4] = o;
    }
}

// ---------------------------------------------------------------------------
// bf16 tensor-core GEMM + max-over-q epilogue (mma.m16n8k16, fp32 accum).
// CTA 128x256, 8 warps (2x4) of 64x64; 3-stage cp.async; ldmatrix fragments.
// ---------------------------------------------------------------------------
__device__ __forceinline__ void mma_bf16(float c[4], unsigned a0, unsigned a1,
                                         unsigned a2, unsigned a3,
                                         unsigned b0, unsigned b1)
{
    asm volatile(
        "mma.sync.aligned.m16n8k16.row.col.f32.bf16.bf16.f32 "
        "{%0,%1,%2,%3},{%4,%5,%6,%7},{%8,%9},{%0,%1,%2,%3};"
        : "+f"(c[0]), "+f"(c[1]), "+f"(c[2]), "+f"(c[3])
        : "r"(a0), "r"(a1), "r"(a2), "r"(a3), "r"(b0), "r"(b1));
}

#define LDSM4(r0, r1, r2, r3, addr) \
    asm volatile("ldmatrix.sync.aligned.m8n8.x4.shared.b16 {%0,%1,%2,%3}, [%4];" \
                 : "=r"(r0), "=r"(r1), "=r"(r2), "=r"(r3) : "r"(addr))

__device__ __forceinline__ void cp16(unsigned saddr, const void* gaddr)
{
    asm volatile("cp.async.cg.shared.global [%0], [%1], 16;"
                 :: "r"(saddr), "l"(gaddr));
}

__global__ __launch_bounds__(256, 1) void sim_tc(const float* __restrict__ temp_p)
{
    extern __shared__ float sm[];
    const int t    = threadIdx.x;
    const int wid  = t >> 5;
    const int lane = t & 31;
    const int g    = lane >> 2;
    const int tg   = lane & 3;
    const int wm   = (wid >> 2) * 64;
    const int wn   = (wid & 3) * 64;
    const int i0   = blockIdx.x * CTA_M;
    const int jq0  = blockIdx.y * CTA_N;

    float c[4][8][4];
#pragma unroll
    for (int mf = 0; mf < 4; mf++)
#pragma unroll
        for (int nf = 0; nf < 8; nf++)
#pragma unroll
            for (int r = 0; r < 4; r++) c[mf][nf][r] = 0.f;

    const unsigned sbase = (unsigned)__cvta_generic_to_shared(sm);
    const __nv_bfloat16* fus = (const __nv_bfloat16*)g_fusion_h;
    const __nv_bfloat16* tgt = (const __nv_bfloat16*)g_target_h;

    // ---- cp.async loader assignments (unchanged swizzle) ----
    const __nv_bfloat16* agp[4]; unsigned aso[4];
#pragma unroll
    for (int p = 0; p < 4; p++) {
        int idx4 = t + p * 256;
        int row = idx4 >> 3, kb = idx4 & 7;
        agp[p] = fus + (size_t)(i0 + row) * DD + kb * 8;
        aso[p] = (unsigned)(row * 128 + ((kb ^ (row & 7)) << 4));
    }
    const __nv_bfloat16* bgp[8]; unsigned bso[8];
#pragma unroll
    for (int p = 0; p < 8; p++) {
        int idx4 = t + p * 256;
        int row = idx4 >> 3, kb = idx4 & 7;
        bgp[p] = tgt + (size_t)(jq0 + row) * DD + kb * 8;
        bso[p] = (unsigned)(A_BYTES + row * 128 + ((kb ^ (row & 7)) << 4));
    }

    // ---- ldmatrix per-lane address bases ----
    // A x4 (per mf): lanes 0-7 rows+0..7/k-lo, 8-15 rows+8/k-lo,
    //                16-23 rows/k-hi, 24-31 rows+8/k-hi
    unsigned a_byte[4]; int a_r7[4];
    const int a_csel = lane >> 4;
#pragma unroll
    for (int mf = 0; mf < 4; mf++) {
        int row = wm + (mf << 4) + (((lane >> 3) & 1) << 3) + (lane & 7);
        a_byte[mf] = (unsigned)(row * 128);
        a_r7[mf] = row & 7;
    }
    // B x4 (per nf-pair p, nf = 2p, 2p+1): lanes 0-7 n(2p)/k-lo, 8-15 n(2p)/k-hi,
    //                16-23 n(2p+1)/k-lo, 24-31 n(2p+1)/k-hi
    unsigned b_byte[4]; int b_r7[4];
    const int b_csel = (lane >> 3) & 1;
#pragma unroll
    for (int p = 0; p < 4; p++) {
        int row = wn + (p << 4) + ((lane >> 4) << 3) + (lane & 7);
        b_byte[p] = (unsigned)(A_BYTES + row * 128);
        b_r7[p] = row & 7;
    }

    // ---- prologue: stage chunks 0, 1 ----
#pragma unroll
    for (int pc = 0; pc < 2; pc++) {
        unsigned sb = sbase + pc * STAGE_BYTES;
#pragma unroll
        for (int p = 0; p < 4; p++) cp16(sb + aso[p], agp[p] + pc * CKH);
#pragma unroll
        for (int p = 0; p < 8; p++) cp16(sb + bso[p], bgp[p] + pc * CKH);
        asm volatile("cp.async.commit_group;" ::: "memory");
    }

    for (int ch = 0; ch < NCHUNK; ch++) {
        if (ch == NCHUNK - 1)
            asm volatile("cp.async.wait_group 0;" ::: "memory");
        else
            asm volatile("cp.async.wait_group 1;" ::: "memory");
        __syncthreads();

        if (ch + 2 < NCHUNK) {
            const int k0 = (ch + 2) * CKH;
            unsigned sb = sbase + (unsigned)(((ch + 2) % NSTAGE) * STAGE_BYTES);
#pragma unroll
            for (int p = 0; p < 4; p++) cp16(sb + aso[p], agp[p] + k0);
#pragma unroll
            for (int p = 0; p < 8; p++) cp16(sb + bso[p], bgp[p] + k0);
            asm volatile("cp.async.commit_group;" ::: "memory");
        }

        const unsigned stg = sbase + (unsigned)((ch % NSTAGE) * STAGE_BYTES);

#pragma unroll
        for (int s = 0; s < 4; s++) {           // 4 k-steps of 16
            unsigned a[4][4];
#pragma unroll
            for (int mf = 0; mf < 4; mf++) {
                unsigned ad = stg + a_byte[mf]
                    + (unsigned)(((((s << 1) | a_csel) ^ a_r7[mf])) << 4);
                LDSM4(a[mf][0], a[mf][1], a[mf][2], a[mf][3], ad);
            }
            unsigned b[8][2];
#pragma unroll
            for (int p = 0; p < 4; p++) {
                unsigned bd = stg + b_byte[p]
                    + (unsigned)(((((s << 1) | b_csel) ^ b_r7[p])) << 4);
                LDSM4(b[2 * p][0], b[2 * p][1], b[2 * p + 1][0], b[2 * p + 1][1], bd);
            }
#pragma unroll
            for (int nf = 0; nf < 8; nf++)
#pragma unroll
                for (int mf = 0; mf < 4; mf++)
                    mma_bf16(c[mf][nf], a[mf][0], a[mf][1], a[mf][2], a[mf][3],
                             b[nf][0], b[nf][1]);
        }
    }

    const float invt = 1.0f / temp_p[0];
#pragma unroll
    for (int mf = 0; mf < 4; mf++) {
#pragma unroll
        for (int h = 0; h < 2; h++) {
#pragma unroll
            for (int jh = 0; jh < 2; jh++) {
                float v = -INFINITY;
#pragma unroll
                for (int nf = 4 * jh; nf < 4 * jh + 4; nf++)
                    v = fmaxf(v, fmaxf(c[mf][nf][2 * h], c[mf][nf][2 * h + 1]));
                v = fmaxf(v, __shfl_xor_sync(0xffffffffu, v, 1));
                v = fmaxf(v, __shfl_xor_sync(0xffffffffu, v, 2));
                if (tg == 0) {
                    int row = i0 + wm + (mf << 4) + (h << 3) + g;
                    int j   = ((jq0 + wn) >> 5) + jh;
                    g_simmax[(size_t)row * BB + j] = v * invt;
                }
            }
        }
    }
}

// ---------------------------------------------------------------------------
// Per-row loss: one warp per row, values in registers, exact top-512 via
// 32-step binary search with __reduce_add_sync.
// ---------------------------------------------------------------------------
__device__ __forceinline__ unsigned f2key(float f)
{
    unsigned b = __float_as_uint(f);
    return (b & 0x80000000u) ? ~b : (b | 0x80000000u);
}
__device__ __forceinline__ float key2f(unsigned k)
{
    return __uint_as_float((k & 0x80000000u) ? (k ^ 0x80000000u) : ~k);
}

__global__ __launch_bounds__(256) void loss_warp()
{
    const int lane = threadIdx.x & 31;
    const int i = (blockIdx.x << 3) + (threadIdx.x >> 5);
    const float* rowp = g_simmax + (size_t)i * BB;

    float v[32];
    float m = -INFINITY, posl = 0.f;
#pragma unroll
    for (int r = 0; r < 32; r++) {
        v[r] = rowp[(r << 5) + lane];
        m = fmaxf(m, v[r]);
        if ((r << 5) + lane == i) posl = v[r];
    }
#pragma unroll
    for (int s = 16; s >= 1; s >>= 1)
        m = fmaxf(m, __shfl_xor_sync(0xffffffffu, m, s));
    float pos = posl;
#pragma unroll
    for (int s = 16; s >= 1; s >>= 1)
        pos += __shfl_xor_sync(0xffffffffu, pos, s);

    float ev[32]; unsigned key[32];
    float sum = 0.f;
#pragma unroll
    for (int r = 0; r < 32; r++) {
        ev[r] = expf(v[r] - m);
        sum += ev[r];
        key[r] = ((r << 5) + lane == i) ? 0u : f2key(v[r]);
    }
#pragma unroll
    for (int s = 16; s >= 1; s >>= 1)
        sum += __shfl_xor_sync(0xffffffffu, sum, s);
    const float lse_all = logf(sum) + m;

    unsigned lo = 0u, hi = 0xFFFFFFFFu;
    for (int it = 0; it < 32; it++) {
        unsigned mid = lo + ((hi - lo) >> 1);
        unsigned cl = 0;
#pragma unroll
        for (int r = 0; r < 32; r++) cl += (key[r] > mid);
        unsigned cnt = __reduce_add_sync(0xffffffffu, cl);
        if (cnt >= NUM_HARD) lo = mid; else hi = mid;
    }

    unsigned cgl = 0; float hsum = 0.f;
#pragma unroll
    for (int r = 0; r < 32; r++) {
        if (key[r] > hi) { cgl++; hsum += ev[r]; }
    }
    unsigned cgt = __reduce_add_sync(0xffffffffu, cgl);
#pragma unroll
    for (int s = 16; s >= 1; s >>= 1)
        hsum += __shfl_xor_sync(0xffffffffu, hsum, s);
    hsum += (float)(NUM_HARD - cgt) * expf(key2f(hi) - m) + expf(pos - m);

    if (lane == 0) {
        const float lse_h = logf(hsum) + m;
        g_rowloss[i] = (lse_all - pos) + 0.5f * (lse_h - pos);
    }
}

__global__ __launch_bounds__(256) void final_kernel(float* __restrict__ out)
{
    __shared__ float red[256];
    const int t = threadIdx.x;
    float s = 0.f;
#pragma unroll
    for (int p = 0; p < 4; p++) s += g_rowloss[t + p * 256];
    red[t] = s;
    __syncthreads();
    for (int st = 128; st > 0; st >>= 1) {
        if (t < st) red[t] += red[t + st];
        __syncthreads();
    }
    if (t == 0) out[0] = red[0] / (float)BB;
}

extern "C" void kernel_launch(void* const* d_in, const int* in_sizes, int n_in,
                              void* d_out, int out_size)
{
    const float* fusion = (const float*)d_in[0];
    const float* target = (const float*)d_in[1];
    const float* temp   = (const float*)d_in[2];
    float* out = (float*)d_out;

    cudaFuncSetAttribute(sim_tc, cudaFuncAttributeMaxDynamicSharedMemorySize,
                         SMEM_BYTES);

    cvt_bf16_kernel<<<2048, 256>>>((const float4*)fusion, (const float4*)target);

    dim3 grid(BB / CTA_M, NJQ / CTA_N);   // (8, 128)
    sim_tc<<<grid, 256, SMEM_BYTES>>>(temp);

    loss_warp<<<BB / 8, 256>>>();
    final_kernel<<<1, 256>>>(out);
}

// round 10
// speedup vs baseline: 8.1777x; 1.0031x over previous
#include <cuda_runtime.h>
#include <cuda_bf16.h>
#include <math.h>
#include <stdint.h>

#define BB 1024
#define QQ 32
#define DD 512
#define NJQ (BB * QQ)
#define NUM_HARD 512

#define CTA_M 128
#define CTA_N 256
#define CKH   64                         // K halves per chunk (128 B/row)
#define NCHUNK (DD / CKH)                // 8
#define A_BYTES (CTA_M * CKH * 2)        // 16384
#define B_BYTES (CTA_N * CKH * 2)        // 32768
#define STAGE_BYTES (A_BYTES + B_BYTES)  // 49152
#define NSTAGE 4
#define SMEM_BYTES (NSTAGE * STAGE_BYTES) // 196608

#define FN4 (BB * DD / 4)

__device__ float g_simmax[BB * BB];
__device__ float g_rowloss[BB];
__device__ unsigned g_done;
__device__ uint4 g_fusion_h[BB * DD / 8];
__device__ uint4 g_target_h[NJQ * DD / 8];

// ---------------------------------------------------------------------------
// fp32 -> bf16 (RNE) conversion, both tensors; also resets completion counter
// ---------------------------------------------------------------------------
__global__ __launch_bounds__(256) void cvt_bf16_kernel(
    const float4* __restrict__ fus, const float4* __restrict__ tgt)
{
    if (blockIdx.x == 0 && threadIdx.x == 0) g_done = 0;
    const int n4 = FN4 + NJQ * DD / 4;
    for (int i = blockIdx.x * blockDim.x + threadIdx.x; i < n4;
         i += gridDim.x * blockDim.x) {
        const bool isf = (i < FN4);
        float4 v = isf ? fus[i] : tgt[i - FN4];
        __nv_bfloat162 h0 = __float22bfloat162_rn(make_float2(v.x, v.y));
        __nv_bfloat162 h1 = __float22bfloat162_rn(make_float2(v.z, v.w));
        uint2 o;
        o.x = *(unsigned*)&h0;
        o.y = *(unsigned*)&h1;
        if (isf) ((uint2*)g_fusion_h)[i] = o;
        else     ((uint2*)g_target_h)[i - FN4] = o;
    }
}

// ---------------------------------------------------------------------------
// bf16 tensor-core GEMM + max-over-q epilogue (mma.m16n8k16, fp32 accum).
// CTA 128x256, 8 warps (2x4) of 64x64; 4-stage cp.async; ldmatrix fragments.
// ---------------------------------------------------------------------------
__device__ __forceinline__ void mma_bf16(float c[4], unsigned a0, unsigned a1,
                                         unsigned a2, unsigned a3,
                                         unsigned b0, unsigned b1)
{
    asm volatile(
        "mma.sync.aligned.m16n8k16.row.col.f32.bf16.bf16.f32 "
        "{%0,%1,%2,%3},{%4,%5,%6,%7},{%8,%9},{%0,%1,%2,%3};"
        : "+f"(c[0]), "+f"(c[1]), "+f"(c[2]), "+f"(c[3])
        : "r"(a0), "r"(a1), "r"(a2), "r"(a3), "r"(b0), "r"(b1));
}

#define LDSM4(r0, r1, r2, r3, addr) \
    asm volatile("ldmatrix.sync.aligned.m8n8.x4.shared.b16 {%0,%1,%2,%3}, [%4];" \
                 : "=r"(r0), "=r"(r1), "=r"(r2), "=r"(r3) : "r"(addr))

__device__ __forceinline__ void cp16(unsigned saddr, const void* gaddr)
{
    asm volatile("cp.async.cg.shared.global [%0], [%1], 16;"
                 :: "r"(saddr), "l"(gaddr));
}

__global__ __launch_bounds__(256, 1) void sim_tc(const float* __restrict__ temp_p)
{
    extern __shared__ float sm[];
    const int t    = threadIdx.x;
    const int wid  = t >> 5;
    const int lane = t & 31;
    const int g    = lane >> 2;
    const int tg   = lane & 3;
    const int wm   = (wid >> 2) * 64;
    const int wn   = (wid & 3) * 64;
    const int i0   = blockIdx.x * CTA_M;
    const int jq0  = blockIdx.y * CTA_N;

    float c[4][8][4];
#pragma unroll
    for (int mf = 0; mf < 4; mf++)
#pragma unroll
        for (int nf = 0; nf < 8; nf++)
#pragma unroll
            for (int r = 0; r < 4; r++) c[mf][nf][r] = 0.f;

    const unsigned sbase = (unsigned)__cvta_generic_to_shared(sm);
    const __nv_bfloat16* fus = (const __nv_bfloat16*)g_fusion_h;
    const __nv_bfloat16* tgt = (const __nv_bfloat16*)g_target_h;

    const __nv_bfloat16* agp[4]; unsigned aso[4];
#pragma unroll
    for (int p = 0; p < 4; p++) {
        int idx4 = t + p * 256;
        int row = idx4 >> 3, kb = idx4 & 7;
        agp[p] = fus + (size_t)(i0 + row) * DD + kb * 8;
        aso[p] = (unsigned)(row * 128 + ((kb ^ (row & 7)) << 4));
    }
    const __nv_bfloat16* bgp[8]; unsigned bso[8];
#pragma unroll
    for (int p = 0; p < 8; p++) {
        int idx4 = t + p * 256;
        int row = idx4 >> 3, kb = idx4 & 7;
        bgp[p] = tgt + (size_t)(jq0 + row) * DD + kb * 8;
        bso[p] = (unsigned)(A_BYTES + row * 128 + ((kb ^ (row & 7)) << 4));
    }

    unsigned a_byte[4]; int a_r7[4];
    const int a_csel = lane >> 4;
#pragma unroll
    for (int mf = 0; mf < 4; mf++) {
        int row = wm + (mf << 4) + (((lane >> 3) & 1) << 3) + (lane & 7);
        a_byte[mf] = (unsigned)(row * 128);
        a_r7[mf] = row & 7;
    }
    unsigned b_byte[4]; int b_r7[4];
    const int b_csel = (lane >> 3) & 1;
#pragma unroll
    for (int p = 0; p < 4; p++) {
        int row = wn + (p << 4) + ((lane >> 4) << 3) + (lane & 7);
        b_byte[p] = (unsigned)(A_BYTES + row * 128);
        b_r7[p] = row & 7;
    }

    // prologue: stage chunks 0, 1, 2
#pragma unroll
    for (int pc = 0; pc < 3; pc++) {
        unsigned sb = sbase + pc * STAGE_BYTES;
#pragma unroll
        for (int p = 0; p < 4; p++) cp16(sb + aso[p], agp[p] + pc * CKH);
#pragma unroll
        for (int p = 0; p < 8; p++) cp16(sb + bso[p], bgp[p] + pc * CKH);
        asm volatile("cp.async.commit_group;" ::: "memory");
    }

    for (int ch = 0; ch < NCHUNK; ch++) {
        if (ch >= NCHUNK - 1)
            asm volatile("cp.async.wait_group 0;" ::: "memory");
        else if (ch == NCHUNK - 2)
            asm volatile("cp.async.wait_group 1;" ::: "memory");
        else
            asm volatile("cp.async.wait_group 2;" ::: "memory");
        __syncthreads();

        if (ch + 3 < NCHUNK) {
            const int k0 = (ch + 3) * CKH;
            unsigned sb = sbase + (unsigned)(((ch + 3) % NSTAGE) * STAGE_BYTES);
#pragma unroll
            for (int p = 0; p < 4; p++) cp16(sb + aso[p], agp[p] + k0);
#pragma unroll
            for (int p = 0; p < 8; p++) cp16(sb + bso[p], bgp[p] + k0);
            asm volatile("cp.async.commit_group;" ::: "memory");
        }

        const unsigned stg = sbase + (unsigned)((ch % NSTAGE) * STAGE_BYTES);

#pragma unroll
        for (int s = 0; s < 4; s++) {
            unsigned a[4][4];
#pragma unroll
            for (int mf = 0; mf < 4; mf++) {
                unsigned ad = stg + a_byte[mf]
                    + (unsigned)(((((s << 1) | a_csel) ^ a_r7[mf])) << 4);
                LDSM4(a[mf][0], a[mf][1], a[mf][2], a[mf][3], ad);
            }
            unsigned b[8][2];
#pragma unroll
            for (int p = 0; p < 4; p++) {
                unsigned bd = stg + b_byte[p]
                    + (unsigned)(((((s << 1) | b_csel) ^ b_r7[p])) << 4);
                LDSM4(b[2 * p][0], b[2 * p][1], b[2 * p + 1][0], b[2 * p + 1][1], bd);
            }
#pragma unroll
            for (int nf = 0; nf < 8; nf++)
#pragma unroll
                for (int mf = 0; mf < 4; mf++)
                    mma_bf16(c[mf][nf], a[mf][0], a[mf][1], a[mf][2], a[mf][3],
                             b[nf][0], b[nf][1]);
        }
    }

    const float invt = 1.0f / temp_p[0];
#pragma unroll
    for (int mf = 0; mf < 4; mf++) {
#pragma unroll
        for (int h = 0; h < 2; h++) {
#pragma unroll
            for (int jh = 0; jh < 2; jh++) {
                float v = -INFINITY;
#pragma unroll
                for (int nf = 4 * jh; nf < 4 * jh + 4; nf++)
                    v = fmaxf(v, fmaxf(c[mf][nf][2 * h], c[mf][nf][2 * h + 1]));
                v = fmaxf(v, __shfl_xor_sync(0xffffffffu, v, 1));
                v = fmaxf(v, __shfl_xor_sync(0xffffffffu, v, 2));
                if (tg == 0) {
                    int row = i0 + wm + (mf << 4) + (h << 3) + g;
                    int j   = ((jq0 + wn) >> 5) + jh;
                    g_simmax[(size_t)row * BB + j] = v * invt;
                }
            }
        }
    }
}

// ---------------------------------------------------------------------------
// Per-row loss: one warp per row (256 blocks x 4 warps -> all SMs), exact
// top-512 via 32-step binary search. Last finished block reduces g_rowloss
// to the scalar output in fixed order (deterministic).
// ---------------------------------------------------------------------------
__device__ __forceinline__ unsigned f2key(float f)
{
    unsigned b = __float_as_uint(f);
    return (b & 0x80000000u) ? ~b : (b | 0x80000000u);
}
__device__ __forceinline__ float key2f(unsigned k)
{
    return __uint_as_float((k & 0x80000000u) ? (k ^ 0x80000000u) : ~k);
}

__global__ __launch_bounds__(128) void loss_warp(float* __restrict__ out)
{
    __shared__ float red[128];
    __shared__ bool s_last;

    const int lane = threadIdx.x & 31;
    const int i = (blockIdx.x << 2) + (threadIdx.x >> 5);
    const float* rowp = g_simmax + (size_t)i * BB;

    float v[32];
    float m = -INFINITY, posl = 0.f;
#pragma unroll
    for (int r = 0; r < 32; r++) {
        v[r] = rowp[(r << 5) + lane];
        m = fmaxf(m, v[r]);
        if ((r << 5) + lane == i) posl = v[r];
    }
#pragma unroll
    for (int s = 16; s >= 1; s >>= 1)
        m = fmaxf(m, __shfl_xor_sync(0xffffffffu, m, s));
    float pos = posl;
#pragma unroll
    for (int s = 16; s >= 1; s >>= 1)
        pos += __shfl_xor_sync(0xffffffffu, pos, s);

    float ev[32]; unsigned key[32];
    float sum = 0.f;
#pragma unroll
    for (int r = 0; r < 32; r++) {
        ev[r] = expf(v[r] - m);
        sum += ev[r];
        key[r] = ((r << 5) + lane == i) ? 0u : f2key(v[r]);
    }
#pragma unroll
    for (int s = 16; s >= 1; s >>= 1)
        sum += __shfl_xor_sync(0xffffffffu, sum, s);
    const float lse_all = logf(sum) + m;

    unsigned lo = 0u, hi = 0xFFFFFFFFu;
    for (int it = 0; it < 32; it++) {
        unsigned mid = lo + ((hi - lo) >> 1);
        unsigned cl = 0;
#pragma unroll
        for (int r = 0; r < 32; r++) cl += (key[r] > mid);
        unsigned cnt = __reduce_add_sync(0xffffffffu, cl);
        if (cnt >= NUM_HARD) lo = mid; else hi = mid;
    }

    unsigned cgl = 0; float hsum = 0.f;
#pragma unroll
    for (int r = 0; r < 32; r++) {
        if (key[r] > hi) { cgl++; hsum += ev[r]; }
    }
    unsigned cgt = __reduce_add_sync(0xffffffffu, cgl);
#pragma unroll
    for (int s = 16; s >= 1; s >>= 1)
        hsum += __shfl_xor_sync(0xffffffffu, hsum, s);
    hsum += (float)(NUM_HARD - cgt) * expf(key2f(hi) - m) + expf(pos - m);

    if (lane == 0) {
        const float lse_h = logf(hsum) + m;
        g_rowloss[i] = (lse_all - pos) + 0.5f * (lse_h - pos);
    }

    // ---- last-block-done final reduction (deterministic order) ----
    __syncthreads();
    if (threadIdx.x == 0) {
        __threadfence();
        unsigned prev = atomicAdd(&g_done, 1u);
        s_last = (prev == (BB / 4) - 1);
    }
    __syncthreads();
    if (s_last) {
        const int t = threadIdx.x;
        float s = 0.f;
#pragma unroll
        for (int p = 0; p < 8; p++) s += g_rowloss[t + p * 128];
        red[t] = s;
        __syncthreads();
        for (int st = 64; st > 0; st >>= 1) {
            if (t < st) red[t] += red[t + st];
            __syncthreads();
        }
        if (t == 0) out[0] = red[0] / (float)BB;
    }
}

extern "C" void kernel_launch(void* const* d_in, const int* in_sizes, int n_in,
                              void* d_out, int out_size)
{
    const float* fusion = (const float*)d_in[0];
    const float* target = (const float*)d_in[1];
    const float* temp   = (const float*)d_in[2];
    float* out = (float*)d_out;

    cudaFuncSetAttribute(sim_tc, cudaFuncAttributeMaxDynamicSharedMemorySize,
                         SMEM_BYTES);

    cvt_bf16_kernel<<<2048, 256>>>((const float4*)fusion, (const float4*)target);

    dim3 grid(BB / CTA_M, NJQ / CTA_N);   // (8, 128)
    sim_tc<<<grid, 256, SMEM_BYTES>>>(temp);

    loss_warp<<<BB / 4, 128>>>(out);
}

// round 11
// speedup vs baseline: 8.4367x; 1.0317x over previous
#include <cuda_runtime.h>
#include <cuda_bf16.h>
#include <math.h>
#include <stdint.h>

#define BB 1024
#define QQ 32
#define DD 512
#define NJQ (BB * QQ)
#define NUM_HARD 512

#define CTA_M 128
#define CTA_N 256
#define CKH   64                         // K halves per chunk (128 B/row)
#define NCHUNK (DD / CKH)                // 8
#define A_BYTES (CTA_M * CKH * 2)        // 16384
#define B_BYTES (CTA_N * CKH * 2)        // 32768
#define STAGE_BYTES (A_BYTES + B_BYTES)  // 49152
#define NSTAGE 4
#define SMEM_BYTES (NSTAGE * STAGE_BYTES) // 196608
#define NTHR 512

#define FN4 (BB * DD / 4)

__device__ float g_simmax[BB * BB];
__device__ float g_rowloss[BB];
__device__ unsigned g_done;
__device__ uint4 g_fusion_h[BB * DD / 8];
__device__ uint4 g_target_h[NJQ * DD / 8];

// ---------------------------------------------------------------------------
// fp32 -> bf16 (RNE) conversion, both tensors; resets completion counter
// ---------------------------------------------------------------------------
__global__ __launch_bounds__(256) void cvt_bf16_kernel(
    const float4* __restrict__ fus, const float4* __restrict__ tgt)
{
    if (blockIdx.x == 0 && threadIdx.x == 0) g_done = 0;
    const int n4 = FN4 + NJQ * DD / 4;
    for (int i = blockIdx.x * blockDim.x + threadIdx.x; i < n4;
         i += gridDim.x * blockDim.x) {
        const bool isf = (i < FN4);
        float4 v = isf ? fus[i] : tgt[i - FN4];
        __nv_bfloat162 h0 = __float22bfloat162_rn(make_float2(v.x, v.y));
        __nv_bfloat162 h1 = __float22bfloat162_rn(make_float2(v.z, v.w));
        uint2 o;
        o.x = *(unsigned*)&h0;
        o.y = *(unsigned*)&h1;
        if (isf) ((uint2*)g_fusion_h)[i] = o;
        else     ((uint2*)g_target_h)[i - FN4] = o;
    }
}

// ---------------------------------------------------------------------------
// bf16 tensor-core GEMM + max-over-q epilogue (mma.m16n8k16, fp32 accum).
// CTA 128x256, 16 warps (2x8) of 64x32 each -> 4 warps/SMSP for issue overlap.
// 4-stage cp.async; ldmatrix fragments; swizzle: 16B chunk c ^ (row&7).
// ---------------------------------------------------------------------------
__device__ __forceinline__ void mma_bf16(float c[4], unsigned a0, unsigned a1,
                                         unsigned a2, unsigned a3,
                                         unsigned b0, unsigned b1)
{
    asm volatile(
        "mma.sync.aligned.m16n8k16.row.col.f32.bf16.bf16.f32 "
        "{%0,%1,%2,%3},{%4,%5,%6,%7},{%8,%9},{%0,%1,%2,%3};"
        : "+f"(c[0]), "+f"(c[1]), "+f"(c[2]), "+f"(c[3])
        : "r"(a0), "r"(a1), "r"(a2), "r"(a3), "r"(b0), "r"(b1));
}

#define LDSM4(r0, r1, r2, r3, addr) \
    asm volatile("ldmatrix.sync.aligned.m8n8.x4.shared.b16 {%0,%1,%2,%3}, [%4];" \
                 : "=r"(r0), "=r"(r1), "=r"(r2), "=r"(r3) : "r"(addr))

__device__ __forceinline__ void cp16(unsigned saddr, const void* gaddr)
{
    asm volatile("cp.async.cg.shared.global [%0], [%1], 16;"
                 :: "r"(saddr), "l"(gaddr));
}

__global__ __launch_bounds__(NTHR, 1) void sim_tc(const float* __restrict__ temp_p)
{
    extern __shared__ float sm[];
    const int t    = threadIdx.x;
    const int wid  = t >> 5;
    const int lane = t & 31;
    const int g    = lane >> 2;
    const int tg   = lane & 3;
    const int wm   = (wid >> 3) * 64;     // 2 warp-rows
    const int wn   = (wid & 7) * 32;      // 8 warp-cols (32 N = one j each)
    const int i0   = blockIdx.x * CTA_M;
    const int jq0  = blockIdx.y * CTA_N;

    float c[4][4][4];
#pragma unroll
    for (int mf = 0; mf < 4; mf++)
#pragma unroll
        for (int nf = 0; nf < 4; nf++)
#pragma unroll
            for (int r = 0; r < 4; r++) c[mf][nf][r] = 0.f;

    const unsigned sbase = (unsigned)__cvta_generic_to_shared(sm);
    const __nv_bfloat16* fus = (const __nv_bfloat16*)g_fusion_h;
    const __nv_bfloat16* tgt = (const __nv_bfloat16*)g_target_h;

    // cp.async loader assignments: A 1024 x 16B -> 2/thread; B 2048 -> 4/thread
    const __nv_bfloat16* agp[2]; unsigned aso[2];
#pragma unroll
    for (int p = 0; p < 2; p++) {
        int idx4 = t + p * NTHR;
        int row = idx4 >> 3, kb = idx4 & 7;
        agp[p] = fus + (size_t)(i0 + row) * DD + kb * 8;
        aso[p] = (unsigned)(row * 128 + ((kb ^ (row & 7)) << 4));
    }
    const __nv_bfloat16* bgp[4]; unsigned bso[4];
#pragma unroll
    for (int p = 0; p < 4; p++) {
        int idx4 = t + p * NTHR;
        int row = idx4 >> 3, kb = idx4 & 7;
        bgp[p] = tgt + (size_t)(jq0 + row) * DD + kb * 8;
        bso[p] = (unsigned)(A_BYTES + row * 128 + ((kb ^ (row & 7)) << 4));
    }

    // ldmatrix per-lane address bases
    unsigned a_byte[4]; int a_r7[4];
    const int a_csel = lane >> 4;
#pragma unroll
    for (int mf = 0; mf < 4; mf++) {
        int row = wm + (mf << 4) + (((lane >> 3) & 1) << 3) + (lane & 7);
        a_byte[mf] = (unsigned)(row * 128);
        a_r7[mf] = row & 7;
    }
    unsigned b_byte[2]; int b_r7[2];
    const int b_csel = (lane >> 3) & 1;
#pragma unroll
    for (int p = 0; p < 2; p++) {
        int row = wn + (p << 4) + ((lane >> 4) << 3) + (lane & 7);
        b_byte[p] = (unsigned)(A_BYTES + row * 128);
        b_r7[p] = row & 7;
    }

    // prologue: stage chunks 0, 1, 2
#pragma unroll
    for (int pc = 0; pc < 3; pc++) {
        unsigned sb = sbase + pc * STAGE_BYTES;
#pragma unroll
        for (int p = 0; p < 2; p++) cp16(sb + aso[p], agp[p] + pc * CKH);
#pragma unroll
        for (int p = 0; p < 4; p++) cp16(sb + bso[p], bgp[p] + pc * CKH);
        asm volatile("cp.async.commit_group;" ::: "memory");
    }

    for (int ch = 0; ch < NCHUNK; ch++) {
        if (ch >= NCHUNK - 1)
            asm volatile("cp.async.wait_group 0;" ::: "memory");
        else if (ch == NCHUNK - 2)
            asm volatile("cp.async.wait_group 1;" ::: "memory");
        else
            asm volatile("cp.async.wait_group 2;" ::: "memory");
        __syncthreads();

        if (ch + 3 < NCHUNK) {
            const int k0 = (ch + 3) * CKH;
            unsigned sb = sbase + (unsigned)(((ch + 3) % NSTAGE) * STAGE_BYTES);
#pragma unroll
            for (int p = 0; p < 2; p++) cp16(sb + aso[p], agp[p] + k0);
#pragma unroll
            for (int p = 0; p < 4; p++) cp16(sb + bso[p], bgp[p] + k0);
            asm volatile("cp.async.commit_group;" ::: "memory");
        }

        const unsigned stg = sbase + (unsigned)((ch % NSTAGE) * STAGE_BYTES);

#pragma unroll
        for (int s = 0; s < 4; s++) {
            unsigned a[4][4];
#pragma unroll
            for (int mf = 0; mf < 4; mf++) {
                unsigned ad = stg + a_byte[mf]
                    + (unsigned)(((((s << 1) | a_csel) ^ a_r7[mf])) << 4);
                LDSM4(a[mf][0], a[mf][1], a[mf][2], a[mf][3], ad);
            }
            unsigned b[4][2];
#pragma unroll
            for (int p = 0; p < 2; p++) {
                unsigned bd = stg + b_byte[p]
                    + (unsigned)(((((s << 1) | b_csel) ^ b_r7[p])) << 4);
                LDSM4(b[2 * p][0], b[2 * p][1], b[2 * p + 1][0], b[2 * p + 1][1], bd);
            }
#pragma unroll
            for (int nf = 0; nf < 4; nf++)
#pragma unroll
                for (int mf = 0; mf < 4; mf++)
                    mma_bf16(c[mf][nf], a[mf][0], a[mf][1], a[mf][2], a[mf][3],
                             b[nf][0], b[nf][1]);
        }
    }

    // epilogue: this warp's 32 N-cols = one j
    const float invt = 1.0f / temp_p[0];
    const int j = (jq0 + wn) >> 5;
#pragma unroll
    for (int mf = 0; mf < 4; mf++) {
#pragma unroll
        for (int h = 0; h < 2; h++) {
            float v = -INFINITY;
#pragma unroll
            for (int nf = 0; nf < 4; nf++)
                v = fmaxf(v, fmaxf(c[mf][nf][2 * h], c[mf][nf][2 * h + 1]));
            v = fmaxf(v, __shfl_xor_sync(0xffffffffu, v, 1));
            v = fmaxf(v, __shfl_xor_sync(0xffffffffu, v, 2));
            if (tg == 0) {
                int row = i0 + wm + (mf << 4) + (h << 3) + g;
                g_simmax[(size_t)row * BB + j] = v * invt;
            }
        }
    }
}

// ---------------------------------------------------------------------------
// Per-row loss: one warp per row; exact top-512 via 32-step binary search.
// Last finished block reduces g_rowloss to the scalar (deterministic order).
// ---------------------------------------------------------------------------
__device__ __forceinline__ unsigned f2key(float f)
{
    unsigned b = __float_as_uint(f);
    return (b & 0x80000000u) ? ~b : (b | 0x80000000u);
}
__device__ __forceinline__ float key2f(unsigned k)
{
    return __uint_as_float((k & 0x80000000u) ? (k ^ 0x80000000u) : ~k);
}

__global__ __launch_bounds__(128) void loss_warp(float* __restrict__ out)
{
    __shared__ float red[128];
    __shared__ bool s_last;

    const int lane = threadIdx.x & 31;
    const int i = (blockIdx.x << 2) + (threadIdx.x >> 5);
    const float* rowp = g_simmax + (size_t)i * BB;

    float v[32];
    float m = -INFINITY, posl = 0.f;
#pragma unroll
    for (int r = 0; r < 32; r++) {
        v[r] = rowp[(r << 5) + lane];
        m = fmaxf(m, v[r]);
        if ((r << 5) + lane == i) posl = v[r];
    }
#pragma unroll
    for (int s = 16; s >= 1; s >>= 1)
        m = fmaxf(m, __shfl_xor_sync(0xffffffffu, m, s));
    float pos = posl;
#pragma unroll
    for (int s = 16; s >= 1; s >>= 1)
        pos += __shfl_xor_sync(0xffffffffu, pos, s);

    float ev[32]; unsigned key[32];
    float sum = 0.f;
#pragma unroll
    for (int r = 0; r < 32; r++) {
        ev[r] = expf(v[r] - m);
        sum += ev[r];
        key[r] = ((r << 5) + lane == i) ? 0u : f2key(v[r]);
    }
#pragma unroll
    for (int s = 16; s >= 1; s >>= 1)
        sum += __shfl_xor_sync(0xffffffffu, sum, s);
    const float lse_all = logf(sum) + m;

    unsigned lo = 0u, hi = 0xFFFFFFFFu;
    for (int it = 0; it < 32; it++) {
        unsigned mid = lo + ((hi - lo) >> 1);
        unsigned cl = 0;
#pragma unroll
        for (int r = 0; r < 32; r++) cl += (key[r] > mid);
        unsigned cnt = __reduce_add_sync(0xffffffffu, cl);
        if (cnt >= NUM_HARD) lo = mid; else hi = mid;
    }

    unsigned cgl = 0; float hsum = 0.f;
#pragma unroll
    for (int r = 0; r < 32; r++) {
        if (key[r] > hi) { cgl++; hsum += ev[r]; }
    }
    unsigned cgt = __reduce_add_sync(0xffffffffu, cgl);
#pragma unroll
    for (int s = 16; s >= 1; s >>= 1)
        hsum += __shfl_xor_sync(0xffffffffu, hsum, s);
    hsum += (float)(NUM_HARD - cgt) * expf(key2f(hi) - m) + expf(pos - m);

    if (lane == 0) {
        const float lse_h = logf(hsum) + m;
        g_rowloss[i] = (lse_all - pos) + 0.5f * (lse_h - pos);
    }

    __syncthreads();
    if (threadIdx.x == 0) {
        __threadfence();
        unsigned prev = atomicAdd(&g_done, 1u);
        s_last = (prev == (BB / 4) - 1);
    }
    __syncthreads();
    if (s_last) {
        const int t = threadIdx.x;
        float s = 0.f;
#pragma unroll
        for (int p = 0; p < 8; p++) s += g_rowloss[t + p * 128];
        red[t] = s;
        __syncthreads();
        for (int st = 64; st > 0; st >>= 1) {
            if (t < st) red[t] += red[t + st];
            __syncthreads();
        }
        if (t == 0) out[0] = red[0] / (float)BB;
    }
}

extern "C" void kernel_launch(void* const* d_in, const int* in_sizes, int n_in,
                              void* d_out, int out_size)
{
    const float* fusion = (const float*)d_in[0];
    const float* target = (const float*)d_in[1];
    const float* temp   = (const float*)d_in[2];
    float* out = (float*)d_out;

    cudaFuncSetAttribute(sim_tc, cudaFuncAttributeMaxDynamicSharedMemorySize,
                         SMEM_BYTES);

    cvt_bf16_kernel<<<2048, 256>>>((const float4*)fusion, (const float4*)target);

    dim3 grid(BB / CTA_M, NJQ / CTA_N);   // (8, 128)
    sim_tc<<<grid, NTHR, SMEM_BYTES>>>(temp);

    loss_warp<<<BB / 4, 128>>>(out);
}

// round 12
// speedup vs baseline: 8.5421x; 1.0125x over previous
#include <cuda_runtime.h>
#include <cuda_bf16.h>
#include <math.h>
#include <stdint.h>

#define BB 1024
#define QQ 32
#define DD 512
#define NJQ (BB * QQ)
#define NUM_HARD 512

#define CTA_M 128
#define CTA_N 128
#define CKH   64                         // K halves per chunk (128 B/row)
#define NCHUNK (DD / CKH)                // 8
#define A_BYTES (CTA_M * CKH * 2)        // 16384
#define B_BYTES (CTA_N * CKH * 2)        // 16384
#define STAGE_BYTES (A_BYTES + B_BYTES)  // 32768
#define NSTAGE 3
#define SMEM_BYTES (NSTAGE * STAGE_BYTES) // 98304 -> 2 CTAs/SM
#define NTHR 256

#define FN4 (BB * DD / 4)

__device__ float g_simmax[BB * BB];
__device__ float g_rowloss[BB];
__device__ unsigned g_done;
__device__ uint4 g_fusion_h[BB * DD / 8];
__device__ uint4 g_target_h[NJQ * DD / 8];

// ---------------------------------------------------------------------------
// fp32 -> bf16 (RNE) conversion, both tensors; resets completion counter
// ---------------------------------------------------------------------------
__global__ __launch_bounds__(256) void cvt_bf16_kernel(
    const float4* __restrict__ fus, const float4* __restrict__ tgt)
{
    if (blockIdx.x == 0 && threadIdx.x == 0) g_done = 0;
    const int n4 = FN4 + NJQ * DD / 4;
    for (int i = blockIdx.x * blockDim.x + threadIdx.x; i < n4;
         i += gridDim.x * blockDim.x) {
        const bool isf = (i < FN4);
        float4 v = isf ? fus[i] : tgt[i - FN4];
        __nv_bfloat162 h0 = __float22bfloat162_rn(make_float2(v.x, v.y));
        __nv_bfloat162 h1 = __float22bfloat162_rn(make_float2(v.z, v.w));
        uint2 o;
        o.x = *(unsigned*)&h0;
        o.y = *(unsigned*)&h1;
        if (isf) ((uint2*)g_fusion_h)[i] = o;
        else     ((uint2*)g_target_h)[i - FN4] = o;
    }
}

// ---------------------------------------------------------------------------
// bf16 tensor-core GEMM + max-over-q epilogue (mma.m16n8k16, fp32 accum).
// CTA 128x128, 8 warps (2x4) of 64x32; 3-stage cp.async; 2 CTAs/SM so the
// per-chunk blockwide sync of one CTA hides under the other CTA's MMA work.
// ---------------------------------------------------------------------------
__device__ __forceinline__ void mma_bf16(float c[4], unsigned a0, unsigned a1,
                                         unsigned a2, unsigned a3,
                                         unsigned b0, unsigned b1)
{
    asm volatile(
        "mma.sync.aligned.m16n8k16.row.col.f32.bf16.bf16.f32 "
        "{%0,%1,%2,%3},{%4,%5,%6,%7},{%8,%9},{%0,%1,%2,%3};"
        : "+f"(c[0]), "+f"(c[1]), "+f"(c[2]), "+f"(c[3])
        : "r"(a0), "r"(a1), "r"(a2), "r"(a3), "r"(b0), "r"(b1));
}

#define LDSM4(r0, r1, r2, r3, addr) \
    asm volatile("ldmatrix.sync.aligned.m8n8.x4.shared.b16 {%0,%1,%2,%3}, [%4];" \
                 : "=r"(r0), "=r"(r1), "=r"(r2), "=r"(r3) : "r"(addr))

__device__ __forceinline__ void cp16(unsigned saddr, const void* gaddr)
{
    asm volatile("cp.async.cg.shared.global [%0], [%1], 16;"
                 :: "r"(saddr), "l"(gaddr));
}

__global__ __launch_bounds__(NTHR, 2) void sim_tc(const float* __restrict__ temp_p)
{
    extern __shared__ float sm[];
    const int t    = threadIdx.x;
    const int wid  = t >> 5;
    const int lane = t & 31;
    const int g    = lane >> 2;
    const int tg   = lane & 3;
    const int wm   = (wid >> 2) * 64;     // 2 warp-rows
    const int wn   = (wid & 3) * 32;      // 4 warp-cols (32 N = one j each)
    const int i0   = blockIdx.x * CTA_M;
    const int jq0  = blockIdx.y * CTA_N;

    float c[4][4][4];
#pragma unroll
    for (int mf = 0; mf < 4; mf++)
#pragma unroll
        for (int nf = 0; nf < 4; nf++)
#pragma unroll
            for (int r = 0; r < 4; r++) c[mf][nf][r] = 0.f;

    const unsigned sbase = (unsigned)__cvta_generic_to_shared(sm);
    const __nv_bfloat16* fus = (const __nv_bfloat16*)g_fusion_h;
    const __nv_bfloat16* tgt = (const __nv_bfloat16*)g_target_h;

    // cp.async loaders: A = B = 1024 x 16B chunks -> 4/thread each
    const __nv_bfloat16* agp[4]; unsigned aso[4];
#pragma unroll
    for (int p = 0; p < 4; p++) {
        int idx4 = t + p * NTHR;
        int row = idx4 >> 3, kb = idx4 & 7;
        agp[p] = fus + (size_t)(i0 + row) * DD + kb * 8;
        aso[p] = (unsigned)(row * 128 + ((kb ^ (row & 7)) << 4));
    }
    const __nv_bfloat16* bgp[4]; unsigned bso[4];
#pragma unroll
    for (int p = 0; p < 4; p++) {
        int idx4 = t + p * NTHR;
        int row = idx4 >> 3, kb = idx4 & 7;
        bgp[p] = tgt + (size_t)(jq0 + row) * DD + kb * 8;
        bso[p] = (unsigned)(A_BYTES + row * 128 + ((kb ^ (row & 7)) << 4));
    }

    // ldmatrix per-lane address bases
    unsigned a_byte[4]; int a_r7[4];
    const int a_csel = lane >> 4;
#pragma unroll
    for (int mf = 0; mf < 4; mf++) {
        int row = wm + (mf << 4) + (((lane >> 3) & 1) << 3) + (lane & 7);
        a_byte[mf] = (unsigned)(row * 128);
        a_r7[mf] = row & 7;
    }
    unsigned b_byte[2]; int b_r7[2];
    const int b_csel = (lane >> 3) & 1;
#pragma unroll
    for (int p = 0; p < 2; p++) {
        int row = wn + (p << 4) + ((lane >> 4) << 3) + (lane & 7);
        b_byte[p] = (unsigned)(A_BYTES + row * 128);
        b_r7[p] = row & 7;
    }

    // prologue: stage chunks 0, 1
#pragma unroll
    for (int pc = 0; pc < 2; pc++) {
        unsigned sb = sbase + pc * STAGE_BYTES;
#pragma unroll
        for (int p = 0; p < 4; p++) cp16(sb + aso[p], agp[p] + pc * CKH);
#pragma unroll
        for (int p = 0; p < 4; p++) cp16(sb + bso[p], bgp[p] + pc * CKH);
        asm volatile("cp.async.commit_group;" ::: "memory");
    }

    for (int ch = 0; ch < NCHUNK; ch++) {
        if (ch == NCHUNK - 1)
            asm volatile("cp.async.wait_group 0;" ::: "memory");
        else
            asm volatile("cp.async.wait_group 1;" ::: "memory");
        __syncthreads();

        if (ch + 2 < NCHUNK) {
            const int k0 = (ch + 2) * CKH;
            unsigned sb = sbase + (unsigned)(((ch + 2) % NSTAGE) * STAGE_BYTES);
#pragma unroll
            for (int p = 0; p < 4; p++) cp16(sb + aso[p], agp[p] + k0);
#pragma unroll
            for (int p = 0; p < 4; p++) cp16(sb + bso[p], bgp[p] + k0);
            asm volatile("cp.async.commit_group;" ::: "memory");
        }

        const unsigned stg = sbase + (unsigned)((ch % NSTAGE) * STAGE_BYTES);

#pragma unroll
        for (int s = 0; s < 4; s++) {
            unsigned a[4][4];
#pragma unroll
            for (int mf = 0; mf < 4; mf++) {
                unsigned ad = stg + a_byte[mf]
                    + (unsigned)(((((s << 1) | a_csel) ^ a_r7[mf])) << 4);
                LDSM4(a[mf][0], a[mf][1], a[mf][2], a[mf][3], ad);
            }
            unsigned b[4][2];
#pragma unroll
            for (int p = 0; p < 2; p++) {
                unsigned bd = stg + b_byte[p]
                    + (unsigned)(((((s << 1) | b_csel) ^ b_r7[p])) << 4);
                LDSM4(b[2 * p][0], b[2 * p][1], b[2 * p + 1][0], b[2 * p + 1][1], bd);
            }
#pragma unroll
            for (int nf = 0; nf < 4; nf++)
#pragma unroll
                for (int mf = 0; mf < 4; mf++)
                    mma_bf16(c[mf][nf], a[mf][0], a[mf][1], a[mf][2], a[mf][3],
                             b[nf][0], b[nf][1]);
        }
    }

    // epilogue: this warp's 32 N-cols = one j
    const float invt = 1.0f / temp_p[0];
    const int j = (jq0 + wn) >> 5;
#pragma unroll
    for (int mf = 0; mf < 4; mf++) {
#pragma unroll
        for (int h = 0; h < 2; h++) {
            float v = -INFINITY;
#pragma unroll
            for (int nf = 0; nf < 4; nf++)
                v = fmaxf(v, fmaxf(c[mf][nf][2 * h], c[mf][nf][2 * h + 1]));
            v = fmaxf(v, __shfl_xor_sync(0xffffffffu, v, 1));
            v = fmaxf(v, __shfl_xor_sync(0xffffffffu, v, 2));
            if (tg == 0) {
                int row = i0 + wm + (mf << 4) + (h << 3) + g;
                g_simmax[(size_t)row * BB + j] = v * invt;
            }
        }
    }
}

// ---------------------------------------------------------------------------
// Per-row loss: one warp per row; exact top-512 via 32-step binary search.
// Last finished block reduces g_rowloss to the scalar (deterministic order).
// ---------------------------------------------------------------------------
__device__ __forceinline__ unsigned f2key(float f)
{
    unsigned b = __float_as_uint(f);
    return (b & 0x80000000u) ? ~b : (b | 0x80000000u);
}
__device__ __forceinline__ float key2f(unsigned k)
{
    return __uint_as_float((k & 0x80000000u) ? (k ^ 0x80000000u) : ~k);
}

__global__ __launch_bounds__(128) void loss_warp(float* __restrict__ out)
{
    __shared__ float red[128];
    __shared__ bool s_last;

    const int lane = threadIdx.x & 31;
    const int i = (blockIdx.x << 2) + (threadIdx.x >> 5);
    const float* rowp = g_simmax + (size_t)i * BB;

    float v[32];
    float m = -INFINITY, posl = 0.f;
#pragma unroll
    for (int r = 0; r < 32; r++) {
        v[r] = rowp[(r << 5) + lane];
        m = fmaxf(m, v[r]);
        if ((r << 5) + lane == i) posl = v[r];
    }
#pragma unroll
    for (int s = 16; s >= 1; s >>= 1)
        m = fmaxf(m, __shfl_xor_sync(0xffffffffu, m, s));
    float pos = posl;
#pragma unroll
    for (int s = 16; s >= 1; s >>= 1)
        pos += __shfl_xor_sync(0xffffffffu, pos, s);

    float ev[32]; unsigned key[32];
    float sum = 0.f;
#pragma unroll
    for (int r = 0; r < 32; r++) {
        ev[r] = expf(v[r] - m);
        sum += ev[r];
        key[r] = ((r << 5) + lane == i) ? 0u : f2key(v[r]);
    }
#pragma unroll
    for (int s = 16; s >= 1; s >>= 1)
        sum += __shfl_xor_sync(0xffffffffu, sum, s);
    const float lse_all = logf(sum) + m;

    unsigned lo = 0u, hi = 0xFFFFFFFFu;
    for (int it = 0; it < 32; it++) {
        unsigned mid = lo + ((hi - lo) >> 1);
        unsigned cl = 0;
#pragma unroll
        for (int r = 0; r < 32; r++) cl += (key[r] > mid);
        unsigned cnt = __reduce_add_sync(0xffffffffu, cl);
        if (cnt >= NUM_HARD) lo = mid; else hi = mid;
    }

    unsigned cgl = 0; float hsum = 0.f;
#pragma unroll
    for (int r = 0; r < 32; r++) {
        if (key[r] > hi) { cgl++; hsum += ev[r]; }
    }
    unsigned cgt = __reduce_add_sync(0xffffffffu, cgl);
#pragma unroll
    for (int s = 16; s >= 1; s >>= 1)
        hsum += __shfl_xor_sync(0xffffffffu, hsum, s);
    hsum += (float)(NUM_HARD - cgt) * expf(key2f(hi) - m) + expf(pos - m);

    if (lane == 0) {
        const float lse_h = logf(hsum) + m;
        g_rowloss[i] = (lse_all - pos) + 0.5f * (lse_h - pos);
    }

    __syncthreads();
    if (threadIdx.x == 0) {
        __threadfence();
        unsigned prev = atomicAdd(&g_done, 1u);
        s_last = (prev == (BB / 4) - 1);
    }
    __syncthreads();
    if (s_last) {
        const int t = threadIdx.x;
        float s = 0.f;
#pragma unroll
        for (int p = 0; p < 8; p++) s += g_rowloss[t + p * 128];
        red[t] = s;
        __syncthreads();
        for (int st = 64; st > 0; st >>= 1) {
            if (t < st) red[t] += red[t + st];
            __syncthreads();
        }
        if (t == 0) out[0] = red[0] / (float)BB;
    }
}

extern "C" void kernel_launch(void* const* d_in, const int* in_sizes, int n_in,
                              void* d_out, int out_size)
{
    const float* fusion = (const float*)d_in[0];
    const float* target = (const float*)d_in[1];
    const float* temp   = (const float*)d_in[2];
    float* out = (float*)d_out;

    cudaFuncSetAttribute(sim_tc, cudaFuncAttributeMaxDynamicSharedMemorySize,
                         SMEM_BYTES);

    cvt_bf16_kernel<<<2048, 256>>>((const float4*)fusion, (const float4*)target);

    dim3 grid(BB / CTA_M, NJQ / CTA_N);   // (8, 256)
    sim_tc<<<grid, NTHR, SMEM_BYTES>>>(temp);

    loss_warp<<<BB / 4, 128>>>(out);
}